// round 2
// baseline (speedup 1.0000x reference)
#include <cuda_runtime.h>
#include <cstdint>

#define BATCH  256
#define DIM    4096
#define BD     (BATCH * DIM)
#define NSTEPS 30
#define KT     32
#define STAGES 3

// Stage layout in dynamic smem (uint32 words): A[256][36] then W[128][36]
#define A_WORDS   (256 * 36)
#define STAGE_WORDS (A_WORDS + 128 * 36)
#define SMEM_BYTES  (STAGES * STAGE_WORDS * 4)

// ---------- persistent device scratch (no allocations allowed) ----------
__device__ uint32_t gW0[(size_t)DIM * DIM];
__device__ uint32_t gW1[(size_t)DIM * DIM];
__device__ uint32_t gW2[(size_t)DIM * DIM];
__device__ uint32_t gW3[(size_t)DIM * DIM];
__device__ uint32_t gW4[(size_t)DIM * DIM];
__device__ float    g_sf[2][3][BD];   // fp32 state, double buffered
__device__ uint32_t g_st[2][3][BD];   // tf32 state copy (MMA operand)
__device__ uint32_t g_s3t[BD];        // tf32 of clamped data layer
__device__ float    g_top[BD];        // s3 @ W4^T (constant across steps)

__device__ __forceinline__ uint32_t f2tf32(float x) {
    uint32_t r;
    asm("cvt.rna.tf32.f32 %0, %1;" : "=r"(r) : "f"(x));
    return r;
}

__device__ __forceinline__ void cp16(uint32_t* sdst, const uint32_t* gsrc) {
    uint32_t sa = (uint32_t)__cvta_generic_to_shared(sdst);
    asm volatile("cp.async.ca.shared.global [%0], [%1], 16;\n" :: "r"(sa), "l"(gsrc));
}
__device__ __forceinline__ void cp_commit() { asm volatile("cp.async.commit_group;\n"); }
__device__ __forceinline__ void cp_wait1()  { asm volatile("cp.async.wait_group 1;\n"); }

__device__ __forceinline__ void mma8(float c[4], const uint32_t a[4], const uint32_t b[2]) {
    asm volatile(
        "mma.sync.aligned.m16n8k8.row.col.f32.tf32.tf32.f32 "
        "{%0,%1,%2,%3},{%4,%5,%6,%7},{%8,%9},{%0,%1,%2,%3};\n"
        : "+f"(c[0]), "+f"(c[1]), "+f"(c[2]), "+f"(c[3])
        : "r"(a[0]), "r"(a[1]), "r"(a[2]), "r"(a[3]), "r"(b[0]), "r"(b[1]));
}

// ---------------- fused GEMM(+update) tile ----------------
// C[256, NT] = A0[256,4096] @ W0p[NT,4096]^T (+ A1 @ W1p^T when nTiles==256)
// epiMode 0: rawOut[idx] = y
// epiMode 1: new = clip(0.5*old + 0.5*(y + bias[col] (+ topP[idx]))), write fp32+tf32
template <int NT>
__device__ __forceinline__ void gemm_tile(
    uint32_t* sm,
    const uint32_t* __restrict__ A0, const uint32_t* __restrict__ W0p,
    const uint32_t* __restrict__ A1, const uint32_t* __restrict__ W1p,
    int nTiles, int nBase, int epiMode,
    const float* __restrict__ oldS, float* __restrict__ newSf,
    uint32_t* __restrict__ newSt, const float* __restrict__ bias,
    const float* __restrict__ topP, float* __restrict__ rawOut)
{
    constexpr int MI  = (NT == 128) ? 4 : 2;   // m16 tiles per warp
    constexpr int WTM = (NT == 128) ? 64 : 32; // warp M extent

    const int tid   = threadIdx.x;
    const int warp  = tid >> 5;
    const int lane  = tid & 31;
    const int lq    = lane >> 2;
    const int lr    = lane & 3;
    const int warpM = (NT == 128) ? (warp >> 2) : (warp >> 1);
    const int warpN = (NT == 128) ? (warp & 3)  : (warp & 1);

    float acc[MI][4][4];
    #pragma unroll
    for (int mi = 0; mi < MI; mi++)
        #pragma unroll
        for (int ni = 0; ni < 4; ni++)
            #pragma unroll
            for (int f = 0; f < 4; f++) acc[mi][ni][f] = 0.0f;

    // ---- async load of one K-tile into stage s ----
    auto load_tile = [&](int s, int t) {
        const uint32_t* A = (t < 128) ? A0 : A1;
        const uint32_t* W = (t < 128) ? W0p : W1p;
        const int kOff = (t & 127) * KT;
        uint32_t* smA = sm + s * STAGE_WORDS;
        uint32_t* smW = smA + A_WORDS;
        #pragma unroll
        for (int j = 0; j < 4; j++) {            // A: 2048 float4
            int f = tid + 512 * j;
            int row = f >> 3, c = (f & 7) * 4;
            cp16(smA + row * 36 + c, A + (size_t)row * DIM + kOff + c);
        }
        if (NT == 128) {
            #pragma unroll
            for (int j = 0; j < 2; j++) {        // W: 1024 float4
                int f = tid + 512 * j;
                int row = f >> 3, c = (f & 7) * 4;
                cp16(smW + row * 36 + c, W + (size_t)row * DIM + kOff + c);
            }
        } else {                                 // W: 512 float4
            int row = tid >> 3, c = (tid & 7) * 4;
            cp16(smW + row * 36 + c, W + (size_t)row * DIM + kOff + c);
        }
    };

    int ld = 0;
    #pragma unroll
    for (int s = 0; s < STAGES - 1; s++) { load_tile(s, ld); cp_commit(); ld++; }

    for (int t = 0; t < nTiles; t++) {
        cp_wait1();
        __syncthreads();
        uint32_t* smA = sm + (t % STAGES) * STAGE_WORDS;
        uint32_t* smW = smA + A_WORDS;

        if (ld < nTiles) { load_tile(ld % STAGES, ld); ld++; }
        cp_commit();

        #pragma unroll
        for (int kk = 0; kk < KT; kk += 8) {
            uint32_t afr[MI][4];
            #pragma unroll
            for (int mi = 0; mi < MI; mi++) {
                int r = warpM * WTM + mi * 16 + lq;
                afr[mi][0] = smA[(r    ) * 36 + kk     + lr];
                afr[mi][1] = smA[(r + 8) * 36 + kk     + lr];
                afr[mi][2] = smA[(r    ) * 36 + kk + 4 + lr];
                afr[mi][3] = smA[(r + 8) * 36 + kk + 4 + lr];
            }
            uint32_t bfr[4][2];
            #pragma unroll
            for (int ni = 0; ni < 4; ni++) {
                int c = warpN * 32 + ni * 8 + lq;
                bfr[ni][0] = smW[c * 36 + kk     + lr];
                bfr[ni][1] = smW[c * 36 + kk + 4 + lr];
            }
            #pragma unroll
            for (int mi = 0; mi < MI; mi++)
                #pragma unroll
                for (int ni = 0; ni < 4; ni++)
                    mma8(acc[mi][ni], afr[mi], bfr[ni]);
        }
    }

    // ---- epilogue (each output element owned by exactly this block) ----
    #pragma unroll
    for (int mi = 0; mi < MI; mi++) {
        #pragma unroll
        for (int ni = 0; ni < 4; ni++) {
            int r0 = warpM * WTM + mi * 16 + lq;
            int c0 = nBase + warpN * 32 + ni * 8 + 2 * lr;
            #pragma unroll
            for (int h = 0; h < 2; h++) {         // rows r0, r0+8
                int r = r0 + 8 * h;
                #pragma unroll
                for (int g = 0; g < 2; g++) {     // cols c0, c0+1
                    int c = c0 + g;
                    float y = acc[mi][ni][2 * h + g];
                    int idx = r * DIM + c;
                    if (epiMode == 0) {
                        rawOut[idx] = y;
                    } else {
                        y += bias[c];
                        if (topP) y += topP[idx];
                        float ns = 0.5f * oldS[idx] + 0.5f * y;
                        ns = fminf(fmaxf(ns, 0.0f), 1.0f);
                        newSf[idx] = ns;
                        newSt[idx] = f2tf32(ns);
                    }
                }
            }
        }
    }
}

// mode 1: top GEMM (grid 32).  mode 0: full fused step (grid 128, one wave).
__global__ void __launch_bounds__(512, 1) step_kernel(
    int p, int mode,
    const float* __restrict__ b0, const float* __restrict__ b2,
    const float* __restrict__ b4)
{
    extern __shared__ uint32_t sm[];
    const int bid = blockIdx.x;
    const int q = p ^ 1;

    if (mode == 1) {
        int nB = bid * 128;
        gemm_tile<128>(sm, g_s3t, gW4 + (size_t)nB * DIM, nullptr, nullptr,
                       128, nB, 0, nullptr, nullptr, nullptr, nullptr, nullptr, g_top);
        return;
    }
    if (bid < 32) {            // s0' <- s1 @ W0^T + b0
        int nB = bid * 128;
        gemm_tile<128>(sm, g_st[p][1], gW0 + (size_t)nB * DIM, nullptr, nullptr,
                       128, nB, 1, g_sf[p][0], g_sf[q][0], g_st[q][0], b0, nullptr, nullptr);
    } else if (bid < 96) {     // s1' <- s2 @ W2^T + s0 @ W1^T + b2   (K=8192)
        int nB = (bid - 32) * 64;
        gemm_tile<64>(sm, g_st[p][2], gW2 + (size_t)nB * DIM,
                      g_st[p][0], gW1 + (size_t)nB * DIM,
                      256, nB, 1, g_sf[p][1], g_sf[q][1], g_st[q][1], b2, nullptr, nullptr);
    } else {                   // s2' <- s1 @ W3^T + top + b4
        int nB = (bid - 96) * 128;
        gemm_tile<128>(sm, g_st[p][1], gW3 + (size_t)nB * DIM, nullptr, nullptr,
                       128, nB, 1, g_sf[p][2], g_sf[q][2], g_st[q][2], b4, g_top, nullptr);
    }
}

// Convert the 5 weight matrices to tf32 once per call.
__global__ void wconv_kernel(const float* __restrict__ w0, const float* __restrict__ w1,
                             const float* __restrict__ w2, const float* __restrict__ w3,
                             const float* __restrict__ w4)
{
    const float* src;
    uint32_t* dst;
    switch (blockIdx.y) {
        case 0: src = w0; dst = gW0; break;
        case 1: src = w1; dst = gW1; break;
        case 2: src = w2; dst = gW2; break;
        case 3: src = w3; dst = gW3; break;
        default: src = w4; dst = gW4; break;
    }
    size_t i = ((size_t)blockIdx.x * blockDim.x + threadIdx.x) * 4;
    float4 v = *(const float4*)(src + i);
    uint4 o;
    o.x = f2tf32(v.x); o.y = f2tf32(v.y); o.z = f2tf32(v.z); o.w = f2tf32(v.w);
    *(uint4*)(dst + i) = o;
}

__global__ void init_kernel(const float* __restrict__ s0, const float* __restrict__ s1,
                            const float* __restrict__ s2, const float* __restrict__ s3)
{
    int i = blockIdx.x * blockDim.x + threadIdx.x;
    float v0 = s0[i], v1 = s1[i], v2 = s2[i];
    g_sf[0][0][i] = v0; g_st[0][0][i] = f2tf32(v0);
    g_sf[0][1][i] = v1; g_st[0][1][i] = f2tf32(v1);
    g_sf[0][2][i] = v2; g_st[0][2][i] = f2tf32(v2);
    g_s3t[i] = f2tf32(s3[i]);
}

__global__ void out_kernel(float* __restrict__ out)
{
    int i = blockIdx.x * blockDim.x + threadIdx.x;
    out[i]          = g_sf[0][0][i];
    out[BD + i]     = g_sf[0][1][i];
    out[2 * BD + i] = g_sf[0][2][i];
}

extern "C" void kernel_launch(void* const* d_in, const int* in_sizes, int n_in,
                              void* d_out, int out_size)
{
    const float* s0 = (const float*)d_in[0];
    const float* s1 = (const float*)d_in[1];
    const float* s2 = (const float*)d_in[2];
    const float* s3 = (const float*)d_in[3];
    const float* W0 = (const float*)d_in[4];
    const float* b0 = (const float*)d_in[5];
    const float* W1 = (const float*)d_in[6];
    const float* W2 = (const float*)d_in[7];
    const float* b2 = (const float*)d_in[8];
    const float* W3 = (const float*)d_in[9];
    const float* W4 = (const float*)d_in[10];
    const float* b4 = (const float*)d_in[11];

    static_assert(SMEM_BYTES <= 227 * 1024, "smem budget");
    cudaFuncSetAttribute(step_kernel, cudaFuncAttributeMaxDynamicSharedMemorySize, SMEM_BYTES);

    wconv_kernel<<<dim3(DIM * DIM / 4 / 256, 5), 256>>>(W0, W1, W2, W3, W4);
    init_kernel<<<BD / 256, 256>>>(s0, s1, s2, s3);

    // top = s3 @ W4^T (b4 folded into the layer-2 epilogue)
    step_kernel<<<32, 512, SMEM_BYTES>>>(0, 1, b0, b2, b4);

    for (int t = 0; t < NSTEPS; t++)
        step_kernel<<<128, 512, SMEM_BYTES>>>(t & 1, 0, b0, b2, b4);

    out_kernel<<<BD / 256, 256>>>((float*)d_out);
}